// round 13
// baseline (speedup 1.0000x reference)
#include <cuda_runtime.h>
#include <cuda_fp16.h>
#include <cstdint>

// N=100000 nodes, d=64, E=3200000 edges, 3 layers.
#define MAXN 100000
#define MAXE 3200000
#define DIM  64
#define PAD  96     // padded-ELL row capacity; P(Poisson(32) >= 96) ~ 4e-20

// Static device scratch (no allocations allowed).
__device__ int     g_cursor[MAXN];
__device__ int2    g_epack[(size_t)MAXN * PAD];   // {col*128 byte-offset, val as dup'd half2}
__device__ __half2 g_xh[2][MAXN * DIM / 2];       // fp16 ping-pong gather tables (row=128B)

// ---------------------------------------------------------------------------
__device__ __forceinline__ int half2bits(float v) {
    __half2 h = __half2half2(__float2half_rn(v));
    return *reinterpret_cast<int*>(&h);
}
__device__ __forceinline__ __half2 u2h(uint32_t u) { return *reinterpret_cast<__half2*>(&u); }
__device__ __forceinline__ __half2 i2h(int u)      { return *reinterpret_cast<__half2*>(&u); }

// cursor init + fp32->fp16 table conversion in one launch
__global__ void k_prep(const float* __restrict__ x, __half2* __restrict__ xh, int n) {
    int i = blockIdx.x * blockDim.x + threadIdx.x;
    if (i < n) g_cursor[i] = i * PAD;
    if (i < n * 32) {
        float2 f = *reinterpret_cast<const float2*>(x + 2 * i);
        xh[i] = __float22half2_rn(f);
    }
}

// scatter edges into padded row slots (4 edges/thread); pack = {col*128, v_half2}
// input streams are read-once -> __ldcs to avoid cache pollution
__global__ void k_scatter(const int* __restrict__ rows,
                          const int* __restrict__ cols,
                          const float* __restrict__ vals, int e) {
    int i = (blockIdx.x * blockDim.x + threadIdx.x) * 4;
    if (i + 3 < e) {
        int4   r4 = __ldcs(reinterpret_cast<const int4*>(rows + i));
        int4   c4 = __ldcs(reinterpret_cast<const int4*>(cols + i));
        float4 v4 = __ldcs(reinterpret_cast<const float4*>(vals + i));
        int p;
        p = atomicAdd(&g_cursor[r4.x], 1); g_epack[p] = make_int2(c4.x << 7, half2bits(v4.x));
        p = atomicAdd(&g_cursor[r4.y], 1); g_epack[p] = make_int2(c4.y << 7, half2bits(v4.y));
        p = atomicAdd(&g_cursor[r4.z], 1); g_epack[p] = make_int2(c4.z << 7, half2bits(v4.z));
        p = atomicAdd(&g_cursor[r4.w], 1); g_epack[p] = make_int2(c4.w << 7, half2bits(v4.w));
    } else {
        for (; i < e; i++) {
            int p = atomicAdd(&g_cursor[rows[i]], 1);
            g_epack[p] = make_int2(cols[i] << 7, half2bits(vals[i]));
        }
    }
}

// zero-pad each row's edge list up to a multiple of 16 with {0, 0.0h} fillers:
// filler gathers read node 0 (broadcast, L1-hot) * 0.0 == exact zero contribution.
__global__ void k_pad(int n) {
    int r = blockIdx.x * blockDim.x + threadIdx.x;
    if (r >= n) return;
    int start = r * PAD;
    int c = g_cursor[r];
    int fin = start + (((c - start) + 15) & ~15);
    for (int i = c; i < fin; i++) g_epack[i] = make_int2(0, 0);
}

// ---------------------------------------------------------------------------
// Shared SpMM core: warp = 1 row; 4 groups of 8 lanes; lane owns 16B of the
// 128B fp16 row. 16 edges/iter: both pack int4s and all four gather LDG.128s
// issued up front (4 gathers in flight). TWO INDEPENDENT 2-edge HFMA2 chunks
// joined by an HADD2 tree, then a SINGLE fp32 flush per iteration (half the
// flush instructions of the 2-flush variant, same ILP). Rows are zero-padded
// to a multiple of 16 so the loop is branch-free.
__device__ __forceinline__ void spmm_row(const char* xb, int g, int start, int end,
                                         float2& f0, float2& f1, float2& f2, float2& f3) {
    int fin = start + (((end - start) + 15) & ~15);
    for (int e = start; e < fin; e += 16) {
        int4 pa = *reinterpret_cast<const int4*>(&g_epack[e + 2 * g]);
        int4 pb = *reinterpret_cast<const int4*>(&g_epack[e + 8 + 2 * g]);
        uint4 h0 = *reinterpret_cast<const uint4*>(xb + (uint32_t)pa.x);
        uint4 h1 = *reinterpret_cast<const uint4*>(xb + (uint32_t)pa.z);
        uint4 h2 = *reinterpret_cast<const uint4*>(xb + (uint32_t)pb.x);
        uint4 h3 = *reinterpret_cast<const uint4*>(xb + (uint32_t)pb.z);
        __half2 v0 = i2h(pa.y), v1 = i2h(pa.w);
        __half2 v2 = i2h(pb.y), v3 = i2h(pb.w);

        // chunk A: edges from pa (independent chain)
        __half2 c0 = __hmul2(v0, u2h(h0.x));
        __half2 c1 = __hmul2(v0, u2h(h0.y));
        __half2 c2 = __hmul2(v0, u2h(h0.z));
        __half2 c3 = __hmul2(v0, u2h(h0.w));
        c0 = __hfma2(v1, u2h(h1.x), c0);
        c1 = __hfma2(v1, u2h(h1.y), c1);
        c2 = __hfma2(v1, u2h(h1.z), c2);
        c3 = __hfma2(v1, u2h(h1.w), c3);

        // chunk B: edges from pb (independent chain)
        __half2 d0 = __hmul2(v2, u2h(h2.x));
        __half2 d1 = __hmul2(v2, u2h(h2.y));
        __half2 d2 = __hmul2(v2, u2h(h2.z));
        __half2 d3 = __hmul2(v2, u2h(h2.w));
        d0 = __hfma2(v3, u2h(h3.x), d0);
        d1 = __hfma2(v3, u2h(h3.y), d1);
        d2 = __hfma2(v3, u2h(h3.z), d2);
        d3 = __hfma2(v3, u2h(h3.w), d3);

        // join tree (depth 2, not a serial chain) + single fp32 flush
        c0 = __hadd2(c0, d0);
        c1 = __hadd2(c1, d1);
        c2 = __hadd2(c2, d2);
        c3 = __hadd2(c3, d3);
        float2 t;
        t = __half22float2(c0); f0.x += t.x; f0.y += t.y;
        t = __half22float2(c1); f1.x += t.x; f1.y += t.y;
        t = __half22float2(c2); f2.x += t.x; f2.y += t.y;
        t = __half22float2(c3); f3.x += t.x; f3.y += t.y;
    }

    #pragma unroll
    for (int off = 8; off <= 16; off <<= 1) {
        f0.x += __shfl_xor_sync(0xffffffffu, f0.x, off);
        f0.y += __shfl_xor_sync(0xffffffffu, f0.y, off);
        f1.x += __shfl_xor_sync(0xffffffffu, f1.x, off);
        f1.y += __shfl_xor_sync(0xffffffffu, f1.y, off);
        f2.x += __shfl_xor_sync(0xffffffffu, f2.x, off);
        f2.y += __shfl_xor_sync(0xffffffffu, f2.y, off);
        f3.x += __shfl_xor_sync(0xffffffffu, f3.x, off);
        f3.y += __shfl_xor_sync(0xffffffffu, f3.y, off);
    }
}

// Layers 1-2: write fp32 row into stacked slot + fp16 mirror for next layer.
__global__ __launch_bounds__(256, 8) void k_spmm12(const __half2* __restrict__ xh,
                                                   float*         __restrict__ yf,
                                                   __half2*       __restrict__ yh,
                                                   int n) {
    int gw = (blockIdx.x * blockDim.x + threadIdx.x) >> 5;
    if (gw >= n) return;
    int lane = threadIdx.x & 31;
    int g    = lane >> 3;
    int sub  = lane & 7;
    const char* xb = reinterpret_cast<const char*>(xh) + sub * 16;

    float2 f0 = {0.f, 0.f}, f1 = {0.f, 0.f}, f2 = {0.f, 0.f}, f3 = {0.f, 0.f};
    spmm_row(xb, g, gw * PAD, __ldg(&g_cursor[gw]), f0, f1, f2, f3);

    if (g == 0) {
        size_t rb = (size_t)gw * 256 + sub * 8;
        *reinterpret_cast<float4*>(yf + rb)     = make_float4(f0.x, f0.y, f1.x, f1.y);
        *reinterpret_cast<float4*>(yf + rb + 4) = make_float4(f2.x, f2.y, f3.x, f3.y);

        __half2 h0 = __float22half2_rn(f0);
        __half2 h1 = __float22half2_rn(f1);
        __half2 h2 = __float22half2_rn(f2);
        __half2 h3 = __float22half2_rn(f3);
        uint4 hv;
        hv.x = *reinterpret_cast<uint32_t*>(&h0);
        hv.y = *reinterpret_cast<uint32_t*>(&h1);
        hv.z = *reinterpret_cast<uint32_t*>(&h2);
        hv.w = *reinterpret_cast<uint32_t*>(&h3);
        *reinterpret_cast<uint4*>(yh + (size_t)gw * 32 + sub * 4) = hv;
    }
}

// Layer 3 + fused epilogue. Final outputs (slot3, slot0, mean) are never
// re-read by any kernel -> __stcs streaming stores keep L2 for the gathers.
__global__ __launch_bounds__(256, 8) void k_spmm3(const __half2* __restrict__ xh,
                                                  const float*   __restrict__ emb,
                                                  float*         __restrict__ mean,
                                                  float*         __restrict__ stacked,
                                                  int n) {
    int gw = (blockIdx.x * blockDim.x + threadIdx.x) >> 5;
    if (gw >= n) return;
    int lane = threadIdx.x & 31;
    int g    = lane >> 3;
    int sub  = lane & 7;
    const char* xb = reinterpret_cast<const char*>(xh) + sub * 16;

    float2 f0 = {0.f, 0.f}, f1 = {0.f, 0.f}, f2 = {0.f, 0.f}, f3 = {0.f, 0.f};
    spmm_row(xb, g, gw * PAD, __ldg(&g_cursor[gw]), f0, f1, f2, f3);

    if (g == 0) {
        float4 o0 = make_float4(f0.x, f0.y, f1.x, f1.y);
        float4 o1 = make_float4(f2.x, f2.y, f3.x, f3.y);
        size_t eb = (size_t)gw * 64 + sub * 8;
        size_t sb = (size_t)gw * 256 + sub * 8;

        __stcs(reinterpret_cast<float4*>(stacked + sb + 192),     o0);   // slot 3
        __stcs(reinterpret_cast<float4*>(stacked + sb + 192 + 4), o1);

        float4 a0 = *reinterpret_cast<const float4*>(emb + eb);
        float4 a1 = *reinterpret_cast<const float4*>(emb + eb + 4);
        float4 b0 = __ldcs(reinterpret_cast<const float4*>(stacked + sb + 64));
        float4 b1 = __ldcs(reinterpret_cast<const float4*>(stacked + sb + 68));
        float4 c0 = __ldcs(reinterpret_cast<const float4*>(stacked + sb + 128));
        float4 c1 = __ldcs(reinterpret_cast<const float4*>(stacked + sb + 132));
        __stcs(reinterpret_cast<float4*>(stacked + sb),     a0);         // slot 0
        __stcs(reinterpret_cast<float4*>(stacked + sb + 4), a1);

        float4 m0, m1;
        m0.x = 0.25f * (a0.x + b0.x + c0.x + o0.x);
        m0.y = 0.25f * (a0.y + b0.y + c0.y + o0.y);
        m0.z = 0.25f * (a0.z + b0.z + c0.z + o0.z);
        m0.w = 0.25f * (a0.w + b0.w + c0.w + o0.w);
        m1.x = 0.25f * (a1.x + b1.x + c1.x + o1.x);
        m1.y = 0.25f * (a1.y + b1.y + c1.y + o1.y);
        m1.z = 0.25f * (a1.z + b1.z + c1.z + o1.z);
        m1.w = 0.25f * (a1.w + b1.w + c1.w + o1.w);
        __stcs(reinterpret_cast<float4*>(mean + eb),     m0);
        __stcs(reinterpret_cast<float4*>(mean + eb + 4), m1);
    }
}

extern "C" void kernel_launch(void* const* d_in, const int* in_sizes, int n_in,
                              void* d_out, int out_size) {
    const float* emb  = (const float*)d_in[0];
    const int*   rows = (const int*)  d_in[1];
    const int*   cols = (const int*)  d_in[2];
    const float* vals = (const float*)d_in[3];
    float* out = (float*)d_out;

    int N = in_sizes[0] / DIM;
    int E = in_sizes[1];
    if (N > MAXN) N = MAXN;
    if (E > MAXE) E = MAXE;

    float* mean    = out;
    float* stacked = out + (size_t)N * DIM;   // [N, 4, 64]

    __half2* xh0;  cudaGetSymbolAddress((void**)&xh0, g_xh);
    __half2* xh1 = xh0 + MAXN * DIM / 2;

    k_prep   <<<(N * 32 + 255) / 256, 256>>>(emb, xh0, N);
    k_scatter<<<(E / 4 + 256) / 256, 256>>>(rows, cols, vals, E);
    k_pad    <<<(N + 255) / 256, 256>>>(N);

    int spmm_blocks = (N * 32 + 255) / 256;   // warp per row
    k_spmm12<<<spmm_blocks, 256>>>(xh0, stacked + 1 * DIM, xh1, N);
    k_spmm12<<<spmm_blocks, 256>>>(xh1, stacked + 2 * DIM, xh0, N);
    k_spmm3 <<<spmm_blocks, 256>>>(xh0, emb, mean, stacked, N);
}

// round 14
// speedup vs baseline: 1.2872x; 1.2872x over previous
#include <cuda_runtime.h>
#include <cuda_fp16.h>
#include <cstdint>

// N=100000 nodes, d=64, E=3200000 edges, 3 layers.
#define MAXN 100000
#define MAXE 3200000
#define DIM  64
#define PAD  96     // padded-ELL row capacity; P(Poisson(32) >= 96) ~ 4e-20

// Static device scratch (no allocations allowed).
__device__ int     g_cursor[MAXN];
__device__ int2    g_epack[(size_t)MAXN * PAD];   // {col*128 byte-offset, val as dup'd half2}
__device__ __half2 g_xh[2][MAXN * DIM / 2];       // fp16 ping-pong gather tables (row=128B)

// ---------------------------------------------------------------------------
__device__ __forceinline__ int half2bits(float v) {
    __half2 h = __half2half2(__float2half_rn(v));
    return *reinterpret_cast<int*>(&h);
}
__device__ __forceinline__ __half2 u2h(uint32_t u) { return *reinterpret_cast<__half2*>(&u); }
__device__ __forceinline__ __half2 i2h(int u)      { return *reinterpret_cast<__half2*>(&u); }

// cursor init + fp32->fp16 table conversion in one launch
__global__ void k_prep(const float* __restrict__ x, __half2* __restrict__ xh, int n) {
    int i = blockIdx.x * blockDim.x + threadIdx.x;
    if (i < n) g_cursor[i] = i * PAD;
    if (i < n * 32) {
        float2 f = *reinterpret_cast<const float2*>(x + 2 * i);
        xh[i] = __float22half2_rn(f);
    }
}

// scatter edges into padded row slots (8 edges/thread); pack = {col*128, v_half2}
// input streams are read-once -> __ldcs to avoid cache pollution
__global__ void k_scatter(const int* __restrict__ rows,
                          const int* __restrict__ cols,
                          const float* __restrict__ vals, int e) {
    int i = (blockIdx.x * blockDim.x + threadIdx.x) * 8;
    if (i + 7 < e) {
        #pragma unroll
        for (int q = 0; q < 2; q++) {
            int4   r4 = __ldcs(reinterpret_cast<const int4*>(rows + i + q * 4));
            int4   c4 = __ldcs(reinterpret_cast<const int4*>(cols + i + q * 4));
            float4 v4 = __ldcs(reinterpret_cast<const float4*>(vals + i + q * 4));
            int p;
            p = atomicAdd(&g_cursor[r4.x], 1); g_epack[p] = make_int2(c4.x << 7, half2bits(v4.x));
            p = atomicAdd(&g_cursor[r4.y], 1); g_epack[p] = make_int2(c4.y << 7, half2bits(v4.y));
            p = atomicAdd(&g_cursor[r4.z], 1); g_epack[p] = make_int2(c4.z << 7, half2bits(v4.z));
            p = atomicAdd(&g_cursor[r4.w], 1); g_epack[p] = make_int2(c4.w << 7, half2bits(v4.w));
        }
    } else {
        for (; i < e; i++) {
            int p = atomicAdd(&g_cursor[rows[i]], 1);
            g_epack[p] = make_int2(cols[i] << 7, half2bits(vals[i]));
        }
    }
}

// zero-pad each row's edge list up to a multiple of 16 with {0, 0.0h} fillers:
// filler gathers read node 0 (broadcast, L1-hot) * 0.0 == exact zero contribution.
__global__ void k_pad(int n) {
    int r = blockIdx.x * blockDim.x + threadIdx.x;
    if (r >= n) return;
    int start = r * PAD;
    int c = g_cursor[r];
    int fin = start + (((c - start) + 15) & ~15);
    for (int i = c; i < fin; i++) g_epack[i] = make_int2(0, 0);
}

// ---------------------------------------------------------------------------
// Shared SpMM core (R12 body, FROZEN): warp = 1 row; 4 groups of 8 lanes; lane
// owns 16B of the 128B fp16 row. 16 edges/iter: both pack int4s and all four
// gather LDG.128s issued up front (4 gathers in flight), then TWO INDEPENDENT
// 2-edge HFMA2 chunks each flushed immediately to fp32 (minimal live ranges --
// join-tree and long-chain variants both spilled/serialized and regressed).
__device__ __forceinline__ void spmm_row(const char* xb, int g, int start, int end,
                                         float2& f0, float2& f1, float2& f2, float2& f3) {
    int fin = start + (((end - start) + 15) & ~15);
    for (int e = start; e < fin; e += 16) {
        int4 pa = *reinterpret_cast<const int4*>(&g_epack[e + 2 * g]);
        int4 pb = *reinterpret_cast<const int4*>(&g_epack[e + 8 + 2 * g]);
        uint4 h0 = *reinterpret_cast<const uint4*>(xb + (uint32_t)pa.x);
        uint4 h1 = *reinterpret_cast<const uint4*>(xb + (uint32_t)pa.z);
        uint4 h2 = *reinterpret_cast<const uint4*>(xb + (uint32_t)pb.x);
        uint4 h3 = *reinterpret_cast<const uint4*>(xb + (uint32_t)pb.z);
        __half2 v0 = i2h(pa.y), v1 = i2h(pa.w);
        __half2 v2 = i2h(pb.y), v3 = i2h(pb.w);

        // chunk A: edges from pa
        __half2 c0 = __hmul2(v0, u2h(h0.x));
        __half2 c1 = __hmul2(v0, u2h(h0.y));
        __half2 c2 = __hmul2(v0, u2h(h0.z));
        __half2 c3 = __hmul2(v0, u2h(h0.w));
        c0 = __hfma2(v1, u2h(h1.x), c0);
        c1 = __hfma2(v1, u2h(h1.y), c1);
        c2 = __hfma2(v1, u2h(h1.z), c2);
        c3 = __hfma2(v1, u2h(h1.w), c3);
        float2 t;
        t = __half22float2(c0); f0.x += t.x; f0.y += t.y;
        t = __half22float2(c1); f1.x += t.x; f1.y += t.y;
        t = __half22float2(c2); f2.x += t.x; f2.y += t.y;
        t = __half22float2(c3); f3.x += t.x; f3.y += t.y;

        // chunk B: edges from pb (independent of chunk A)
        c0 = __hmul2(v2, u2h(h2.x));
        c1 = __hmul2(v2, u2h(h2.y));
        c2 = __hmul2(v2, u2h(h2.z));
        c3 = __hmul2(v2, u2h(h2.w));
        c0 = __hfma2(v3, u2h(h3.x), c0);
        c1 = __hfma2(v3, u2h(h3.y), c1);
        c2 = __hfma2(v3, u2h(h3.z), c2);
        c3 = __hfma2(v3, u2h(h3.w), c3);
        t = __half22float2(c0); f0.x += t.x; f0.y += t.y;
        t = __half22float2(c1); f1.x += t.x; f1.y += t.y;
        t = __half22float2(c2); f2.x += t.x; f2.y += t.y;
        t = __half22float2(c3); f3.x += t.x; f3.y += t.y;
    }

    #pragma unroll
    for (int off = 8; off <= 16; off <<= 1) {
        f0.x += __shfl_xor_sync(0xffffffffu, f0.x, off);
        f0.y += __shfl_xor_sync(0xffffffffu, f0.y, off);
        f1.x += __shfl_xor_sync(0xffffffffu, f1.x, off);
        f1.y += __shfl_xor_sync(0xffffffffu, f1.y, off);
        f2.x += __shfl_xor_sync(0xffffffffu, f2.x, off);
        f2.y += __shfl_xor_sync(0xffffffffu, f2.y, off);
        f3.x += __shfl_xor_sync(0xffffffffu, f3.x, off);
        f3.y += __shfl_xor_sync(0xffffffffu, f3.y, off);
    }
}

// Layers 1-2: fp32 row -> stacked slot (streamed; re-read only once, much later)
// + fp16 mirror for the next layer (normal store; gathered next layer -> keep in L2).
__global__ __launch_bounds__(256, 8) void k_spmm12(const __half2* __restrict__ xh,
                                                   float*         __restrict__ yf,
                                                   __half2*       __restrict__ yh,
                                                   int n) {
    int gw = (blockIdx.x * blockDim.x + threadIdx.x) >> 5;
    if (gw >= n) return;
    int lane = threadIdx.x & 31;
    int g    = lane >> 3;
    int sub  = lane & 7;
    const char* xb = reinterpret_cast<const char*>(xh) + sub * 16;

    float2 f0 = {0.f, 0.f}, f1 = {0.f, 0.f}, f2 = {0.f, 0.f}, f3 = {0.f, 0.f};
    spmm_row(xb, g, gw * PAD, __ldg(&g_cursor[gw]), f0, f1, f2, f3);

    if (g == 0) {
        size_t rb = (size_t)gw * 256 + sub * 8;
        __stcs(reinterpret_cast<float4*>(yf + rb),     make_float4(f0.x, f0.y, f1.x, f1.y));
        __stcs(reinterpret_cast<float4*>(yf + rb + 4), make_float4(f2.x, f2.y, f3.x, f3.y));

        __half2 h0 = __float22half2_rn(f0);
        __half2 h1 = __float22half2_rn(f1);
        __half2 h2 = __float22half2_rn(f2);
        __half2 h3 = __float22half2_rn(f3);
        uint4 hv;
        hv.x = *reinterpret_cast<uint32_t*>(&h0);
        hv.y = *reinterpret_cast<uint32_t*>(&h1);
        hv.z = *reinterpret_cast<uint32_t*>(&h2);
        hv.w = *reinterpret_cast<uint32_t*>(&h3);
        *reinterpret_cast<uint4*>(yh + (size_t)gw * 32 + sub * 4) = hv;
    }
}

// Layer 3 + fused epilogue. Final outputs (slot3, slot0, mean) are never
// re-read by any kernel -> __stcs streaming stores keep L2 for the gathers.
__global__ __launch_bounds__(256, 8) void k_spmm3(const __half2* __restrict__ xh,
                                                  const float*   __restrict__ emb,
                                                  float*         __restrict__ mean,
                                                  float*         __restrict__ stacked,
                                                  int n) {
    int gw = (blockIdx.x * blockDim.x + threadIdx.x) >> 5;
    if (gw >= n) return;
    int lane = threadIdx.x & 31;
    int g    = lane >> 3;
    int sub  = lane & 7;
    const char* xb = reinterpret_cast<const char*>(xh) + sub * 16;

    float2 f0 = {0.f, 0.f}, f1 = {0.f, 0.f}, f2 = {0.f, 0.f}, f3 = {0.f, 0.f};
    spmm_row(xb, g, gw * PAD, __ldg(&g_cursor[gw]), f0, f1, f2, f3);

    if (g == 0) {
        float4 o0 = make_float4(f0.x, f0.y, f1.x, f1.y);
        float4 o1 = make_float4(f2.x, f2.y, f3.x, f3.y);
        size_t eb = (size_t)gw * 64 + sub * 8;
        size_t sb = (size_t)gw * 256 + sub * 8;

        __stcs(reinterpret_cast<float4*>(stacked + sb + 192),     o0);   // slot 3
        __stcs(reinterpret_cast<float4*>(stacked + sb + 192 + 4), o1);

        float4 a0 = *reinterpret_cast<const float4*>(emb + eb);
        float4 a1 = *reinterpret_cast<const float4*>(emb + eb + 4);
        float4 b0 = __ldcs(reinterpret_cast<const float4*>(stacked + sb + 64));
        float4 b1 = __ldcs(reinterpret_cast<const float4*>(stacked + sb + 68));
        float4 c0 = __ldcs(reinterpret_cast<const float4*>(stacked + sb + 128));
        float4 c1 = __ldcs(reinterpret_cast<const float4*>(stacked + sb + 132));
        __stcs(reinterpret_cast<float4*>(stacked + sb),     a0);         // slot 0
        __stcs(reinterpret_cast<float4*>(stacked + sb + 4), a1);

        float4 m0, m1;
        m0.x = 0.25f * (a0.x + b0.x + c0.x + o0.x);
        m0.y = 0.25f * (a0.y + b0.y + c0.y + o0.y);
        m0.z = 0.25f * (a0.z + b0.z + c0.z + o0.z);
        m0.w = 0.25f * (a0.w + b0.w + c0.w + o0.w);
        m1.x = 0.25f * (a1.x + b1.x + c1.x + o1.x);
        m1.y = 0.25f * (a1.y + b1.y + c1.y + o1.y);
        m1.z = 0.25f * (a1.z + b1.z + c1.z + o1.z);
        m1.w = 0.25f * (a1.w + b1.w + c1.w + o1.w);
        __stcs(reinterpret_cast<float4*>(mean + eb),     m0);
        __stcs(reinterpret_cast<float4*>(mean + eb + 4), m1);
    }
}

extern "C" void kernel_launch(void* const* d_in, const int* in_sizes, int n_in,
                              void* d_out, int out_size) {
    const float* emb  = (const float*)d_in[0];
    const int*   rows = (const int*)  d_in[1];
    const int*   cols = (const int*)  d_in[2];
    const float* vals = (const float*)d_in[3];
    float* out = (float*)d_out;

    int N = in_sizes[0] / DIM;
    int E = in_sizes[1];
    if (N > MAXN) N = MAXN;
    if (E > MAXE) E = MAXE;

    float* mean    = out;
    float* stacked = out + (size_t)N * DIM;   // [N, 4, 64]

    __half2* xh0;  cudaGetSymbolAddress((void**)&xh0, g_xh);
    __half2* xh1 = xh0 + MAXN * DIM / 2;

    k_prep   <<<(N * 32 + 255) / 256, 256>>>(emb, xh0, N);
    k_scatter<<<(E / 8 + 256) / 256, 256>>>(rows, cols, vals, E);
    k_pad    <<<(N + 255) / 256, 256>>>(N);

    int spmm_blocks = (N * 32 + 255) / 256;   // warp per row
    k_spmm12<<<spmm_blocks, 256>>>(xh0, stacked + 1 * DIM, xh1, N);
    k_spmm12<<<spmm_blocks, 256>>>(xh1, stacked + 2 * DIM, xh0, N);
    k_spmm3 <<<spmm_blocks, 256>>>(xh0, emb, mean, stacked, N);
}

// round 15
// speedup vs baseline: 1.3245x; 1.0289x over previous
#include <cuda_runtime.h>
#include <cuda_fp16.h>
#include <cstdint>

// N=100000 nodes, d=64, E=3200000 edges, 3 layers.
#define MAXN 100000
#define MAXE 3200000
#define DIM  64
#define PAD  96     // padded-ELL row capacity; P(Poisson(32) >= 96) ~ 4e-20

// Static device scratch (no allocations allowed).
__device__ int     g_cursor[MAXN];
__device__ int2    g_epack[(size_t)MAXN * PAD];   // {col*128 byte-offset, val as dup'd half2}
__device__ __half2 g_xh[2][MAXN * DIM / 2];       // fp16 ping-pong gather tables (row=128B)

// ---------------------------------------------------------------------------
__device__ __forceinline__ int half2bits(float v) {
    __half2 h = __half2half2(__float2half_rn(v));
    return *reinterpret_cast<int*>(&h);
}
__device__ __forceinline__ __half2 u2h(uint32_t u) { return *reinterpret_cast<__half2*>(&u); }
__device__ __forceinline__ __half2 i2h(int u)      { return *reinterpret_cast<__half2*>(&u); }

// cursor init + fp32->fp16 table conversion in one launch
__global__ void k_prep(const float* __restrict__ x, __half2* __restrict__ xh, int n) {
    int i = blockIdx.x * blockDim.x + threadIdx.x;
    if (i < n) g_cursor[i] = i * PAD;
    if (i < n * 32) {
        float2 f = *reinterpret_cast<const float2*>(x + 2 * i);
        xh[i] = __float22half2_rn(f);
    }
}

// scatter edges into padded row slots (4 edges/thread -- more threads hide the
// random-store latency better than fatter threads); pack = {col*128, v_half2}
__global__ void k_scatter(const int* __restrict__ rows,
                          const int* __restrict__ cols,
                          const float* __restrict__ vals, int e) {
    int i = (blockIdx.x * blockDim.x + threadIdx.x) * 4;
    if (i + 3 < e) {
        int4   r4 = __ldcs(reinterpret_cast<const int4*>(rows + i));
        int4   c4 = __ldcs(reinterpret_cast<const int4*>(cols + i));
        float4 v4 = __ldcs(reinterpret_cast<const float4*>(vals + i));
        int p;
        p = atomicAdd(&g_cursor[r4.x], 1); g_epack[p] = make_int2(c4.x << 7, half2bits(v4.x));
        p = atomicAdd(&g_cursor[r4.y], 1); g_epack[p] = make_int2(c4.y << 7, half2bits(v4.y));
        p = atomicAdd(&g_cursor[r4.z], 1); g_epack[p] = make_int2(c4.z << 7, half2bits(v4.z));
        p = atomicAdd(&g_cursor[r4.w], 1); g_epack[p] = make_int2(c4.w << 7, half2bits(v4.w));
    } else {
        for (; i < e; i++) {
            int p = atomicAdd(&g_cursor[rows[i]], 1);
            g_epack[p] = make_int2(cols[i] << 7, half2bits(vals[i]));
        }
    }
}

// zero-pad each row's edge list up to a multiple of 16 with {0, 0.0h} fillers:
// filler gathers read node 0 (broadcast, L1-hot) * 0.0 == exact zero contribution.
__global__ void k_pad(int n) {
    int r = blockIdx.x * blockDim.x + threadIdx.x;
    if (r >= n) return;
    int start = r * PAD;
    int c = g_cursor[r];
    int fin = start + (((c - start) + 15) & ~15);
    for (int i = c; i < fin; i++) g_epack[i] = make_int2(0, 0);
}

// ---------------------------------------------------------------------------
// Shared SpMM core (R12 body, FROZEN structure): warp = 1 row; 4 groups of 8
// lanes; lane owns 16B of the 128B fp16 row. 16 edges/iter: both pack int4s
// (__ldcs -- the 77MB epack stream must not evict the 12.8MB gather table from
// L2) and all four gather LDG.128s issued up front, then TWO INDEPENDENT 2-edge
// HFMA2 chunks each flushed immediately to fp32 (minimal live ranges).
__device__ __forceinline__ void spmm_row(const char* xb, int g, int start, int end,
                                         float2& f0, float2& f1, float2& f2, float2& f3) {
    int fin = start + (((end - start) + 15) & ~15);
    for (int e = start; e < fin; e += 16) {
        int4 pa = __ldcs(reinterpret_cast<const int4*>(&g_epack[e + 2 * g]));
        int4 pb = __ldcs(reinterpret_cast<const int4*>(&g_epack[e + 8 + 2 * g]));
        uint4 h0 = *reinterpret_cast<const uint4*>(xb + (uint32_t)pa.x);
        uint4 h1 = *reinterpret_cast<const uint4*>(xb + (uint32_t)pa.z);
        uint4 h2 = *reinterpret_cast<const uint4*>(xb + (uint32_t)pb.x);
        uint4 h3 = *reinterpret_cast<const uint4*>(xb + (uint32_t)pb.z);
        __half2 v0 = i2h(pa.y), v1 = i2h(pa.w);
        __half2 v2 = i2h(pb.y), v3 = i2h(pb.w);

        // chunk A: edges from pa
        __half2 c0 = __hmul2(v0, u2h(h0.x));
        __half2 c1 = __hmul2(v0, u2h(h0.y));
        __half2 c2 = __hmul2(v0, u2h(h0.z));
        __half2 c3 = __hmul2(v0, u2h(h0.w));
        c0 = __hfma2(v1, u2h(h1.x), c0);
        c1 = __hfma2(v1, u2h(h1.y), c1);
        c2 = __hfma2(v1, u2h(h1.z), c2);
        c3 = __hfma2(v1, u2h(h1.w), c3);
        float2 t;
        t = __half22float2(c0); f0.x += t.x; f0.y += t.y;
        t = __half22float2(c1); f1.x += t.x; f1.y += t.y;
        t = __half22float2(c2); f2.x += t.x; f2.y += t.y;
        t = __half22float2(c3); f3.x += t.x; f3.y += t.y;

        // chunk B: edges from pb (independent of chunk A)
        c0 = __hmul2(v2, u2h(h2.x));
        c1 = __hmul2(v2, u2h(h2.y));
        c2 = __hmul2(v2, u2h(h2.z));
        c3 = __hmul2(v2, u2h(h2.w));
        c0 = __hfma2(v3, u2h(h3.x), c0);
        c1 = __hfma2(v3, u2h(h3.y), c1);
        c2 = __hfma2(v3, u2h(h3.z), c2);
        c3 = __hfma2(v3, u2h(h3.w), c3);
        t = __half22float2(c0); f0.x += t.x; f0.y += t.y;
        t = __half22float2(c1); f1.x += t.x; f1.y += t.y;
        t = __half22float2(c2); f2.x += t.x; f2.y += t.y;
        t = __half22float2(c3); f3.x += t.x; f3.y += t.y;
    }

    #pragma unroll
    for (int off = 8; off <= 16; off <<= 1) {
        f0.x += __shfl_xor_sync(0xffffffffu, f0.x, off);
        f0.y += __shfl_xor_sync(0xffffffffu, f0.y, off);
        f1.x += __shfl_xor_sync(0xffffffffu, f1.x, off);
        f1.y += __shfl_xor_sync(0xffffffffu, f1.y, off);
        f2.x += __shfl_xor_sync(0xffffffffu, f2.x, off);
        f2.y += __shfl_xor_sync(0xffffffffu, f2.y, off);
        f3.x += __shfl_xor_sync(0xffffffffu, f3.x, off);
        f3.y += __shfl_xor_sync(0xffffffffu, f3.y, off);
    }
}

// Layers 1-2: fp32 row -> stacked slot (streamed; re-read only once, much later)
// + fp16 mirror for the next layer (normal store; gathered next layer -> keep in L2).
__global__ __launch_bounds__(256, 8) void k_spmm12(const __half2* __restrict__ xh,
                                                   float*         __restrict__ yf,
                                                   __half2*       __restrict__ yh,
                                                   int n) {
    int gw = (blockIdx.x * blockDim.x + threadIdx.x) >> 5;
    if (gw >= n) return;
    int lane = threadIdx.x & 31;
    int g    = lane >> 3;
    int sub  = lane & 7;
    const char* xb = reinterpret_cast<const char*>(xh) + sub * 16;

    float2 f0 = {0.f, 0.f}, f1 = {0.f, 0.f}, f2 = {0.f, 0.f}, f3 = {0.f, 0.f};
    spmm_row(xb, g, gw * PAD, __ldg(&g_cursor[gw]), f0, f1, f2, f3);

    if (g == 0) {
        size_t rb = (size_t)gw * 256 + sub * 8;
        __stcs(reinterpret_cast<float4*>(yf + rb),     make_float4(f0.x, f0.y, f1.x, f1.y));
        __stcs(reinterpret_cast<float4*>(yf + rb + 4), make_float4(f2.x, f2.y, f3.x, f3.y));

        __half2 h0 = __float22half2_rn(f0);
        __half2 h1 = __float22half2_rn(f1);
        __half2 h2 = __float22half2_rn(f2);
        __half2 h3 = __float22half2_rn(f3);
        uint4 hv;
        hv.x = *reinterpret_cast<uint32_t*>(&h0);
        hv.y = *reinterpret_cast<uint32_t*>(&h1);
        hv.z = *reinterpret_cast<uint32_t*>(&h2);
        hv.w = *reinterpret_cast<uint32_t*>(&h3);
        *reinterpret_cast<uint4*>(yh + (size_t)gw * 32 + sub * 4) = hv;
    }
}

// Layer 3 + fused epilogue. Final outputs (slot3, slot0, mean) are never
// re-read by any kernel -> __stcs streaming stores keep L2 for the gathers.
__global__ __launch_bounds__(256, 8) void k_spmm3(const __half2* __restrict__ xh,
                                                  const float*   __restrict__ emb,
                                                  float*         __restrict__ mean,
                                                  float*         __restrict__ stacked,
                                                  int n) {
    int gw = (blockIdx.x * blockDim.x + threadIdx.x) >> 5;
    if (gw >= n) return;
    int lane = threadIdx.x & 31;
    int g    = lane >> 3;
    int sub  = lane & 7;
    const char* xb = reinterpret_cast<const char*>(xh) + sub * 16;

    float2 f0 = {0.f, 0.f}, f1 = {0.f, 0.f}, f2 = {0.f, 0.f}, f3 = {0.f, 0.f};
    spmm_row(xb, g, gw * PAD, __ldg(&g_cursor[gw]), f0, f1, f2, f3);

    if (g == 0) {
        float4 o0 = make_float4(f0.x, f0.y, f1.x, f1.y);
        float4 o1 = make_float4(f2.x, f2.y, f3.x, f3.y);
        size_t eb = (size_t)gw * 64 + sub * 8;
        size_t sb = (size_t)gw * 256 + sub * 8;

        __stcs(reinterpret_cast<float4*>(stacked + sb + 192),     o0);   // slot 3
        __stcs(reinterpret_cast<float4*>(stacked + sb + 192 + 4), o1);

        float4 a0 = *reinterpret_cast<const float4*>(emb + eb);
        float4 a1 = *reinterpret_cast<const float4*>(emb + eb + 4);
        float4 b0 = __ldcs(reinterpret_cast<const float4*>(stacked + sb + 64));
        float4 b1 = __ldcs(reinterpret_cast<const float4*>(stacked + sb + 68));
        float4 c0 = __ldcs(reinterpret_cast<const float4*>(stacked + sb + 128));
        float4 c1 = __ldcs(reinterpret_cast<const float4*>(stacked + sb + 132));
        __stcs(reinterpret_cast<float4*>(stacked + sb),     a0);         // slot 0
        __stcs(reinterpret_cast<float4*>(stacked + sb + 4), a1);

        float4 m0, m1;
        m0.x = 0.25f * (a0.x + b0.x + c0.x + o0.x);
        m0.y = 0.25f * (a0.y + b0.y + c0.y + o0.y);
        m0.z = 0.25f * (a0.z + b0.z + c0.z + o0.z);
        m0.w = 0.25f * (a0.w + b0.w + c0.w + o0.w);
        m1.x = 0.25f * (a1.x + b1.x + c1.x + o1.x);
        m1.y = 0.25f * (a1.y + b1.y + c1.y + o1.y);
        m1.z = 0.25f * (a1.z + b1.z + c1.z + o1.z);
        m1.w = 0.25f * (a1.w + b1.w + c1.w + o1.w);
        __stcs(reinterpret_cast<float4*>(mean + eb),     m0);
        __stcs(reinterpret_cast<float4*>(mean + eb + 4), m1);
    }
}

extern "C" void kernel_launch(void* const* d_in, const int* in_sizes, int n_in,
                              void* d_out, int out_size) {
    const float* emb  = (const float*)d_in[0];
    const int*   rows = (const int*)  d_in[1];
    const int*   cols = (const int*)  d_in[2];
    const float* vals = (const float*)d_in[3];
    float* out = (float*)d_out;

    int N = in_sizes[0] / DIM;
    int E = in_sizes[1];
    if (N > MAXN) N = MAXN;
    if (E > MAXE) E = MAXE;

    float* mean    = out;
    float* stacked = out + (size_t)N * DIM;   // [N, 4, 64]

    __half2* xh0;  cudaGetSymbolAddress((void**)&xh0, g_xh);
    __half2* xh1 = xh0 + MAXN * DIM / 2;

    k_prep   <<<(N * 32 + 255) / 256, 256>>>(emb, xh0, N);
    k_scatter<<<(E / 4 + 256) / 256, 256>>>(rows, cols, vals, E);
    k_pad    <<<(N + 255) / 256, 256>>>(N);

    int spmm_blocks = (N * 32 + 255) / 256;   // warp per row
    k_spmm12<<<spmm_blocks, 256>>>(xh0, stacked + 1 * DIM, xh1, N);
    k_spmm12<<<spmm_blocks, 256>>>(xh1, stacked + 2 * DIM, xh0, N);
    k_spmm3 <<<spmm_blocks, 256>>>(xh0, emb, mean, stacked, N);
}

// round 16
// speedup vs baseline: 1.3516x; 1.0205x over previous
#include <cuda_runtime.h>
#include <cuda_fp16.h>
#include <cstdint>

// N=100000 nodes, d=64, E=3200000 edges, 3 layers.
#define MAXN 100000
#define MAXE 3200000
#define DIM  64
#define PAD  96     // padded-ELL row capacity; P(Poisson(32) >= 96) ~ 4e-20

// Static device scratch (no allocations allowed).
__device__ int     g_cursor[MAXN];
__device__ int2    g_epack[(size_t)MAXN * PAD];   // {col*128 byte-offset, val as dup'd half2}
__device__ __half2 g_xh[2][MAXN * DIM / 2];       // fp16 ping-pong gather tables (row=128B)

// ---------------------------------------------------------------------------
__device__ __forceinline__ int half2bits(float v) {
    __half2 h = __half2half2(__float2half_rn(v));
    return *reinterpret_cast<int*>(&h);
}
__device__ __forceinline__ __half2 u2h(uint32_t u) { return *reinterpret_cast<__half2*>(&u); }
__device__ __forceinline__ __half2 i2h(int u)      { return *reinterpret_cast<__half2*>(&u); }

// packed-fp32 accumulate: acc(f32x2) += cvt_f32x2(half2 c). SASS: 2x F2F + ADD.F32X2
// (sm_103a packed fp32 add; the mov.b64 of fresh cvt temps is elided by ptxas).
__device__ __forceinline__ void acc_h2(unsigned long long& acc, __half2 c) {
    uint32_t cb = *reinterpret_cast<uint32_t*>(&c);
    asm("{\n\t"
        ".reg .b16 l0, h0;\n\t"
        ".reg .b32 lo, hi;\n\t"
        ".reg .b64 t;\n\t"
        "mov.b32 {l0, h0}, %1;\n\t"
        "cvt.f32.f16 lo, l0;\n\t"
        "cvt.f32.f16 hi, h0;\n\t"
        "mov.b64 t, {lo, hi};\n\t"
        "add.rn.f32x2 %0, %0, t;\n\t"
        "}" : "+l"(acc) : "r"(cb));
}
__device__ __forceinline__ float2 unpack64(unsigned long long a) {
    float2 r;
    asm("mov.b64 {%0, %1}, %2;" : "=f"(r.x), "=f"(r.y) : "l"(a));
    return r;
}

// cursor init + fp32->fp16 table conversion in one launch
__global__ void k_prep(const float* __restrict__ x, __half2* __restrict__ xh, int n) {
    int i = blockIdx.x * blockDim.x + threadIdx.x;
    if (i < n) g_cursor[i] = i * PAD;
    if (i < n * 32) {
        float2 f = *reinterpret_cast<const float2*>(x + 2 * i);
        xh[i] = __float22half2_rn(f);
    }
}

// scatter edges into padded row slots (4 edges/thread -- more threads hide the
// random-store latency better than fatter threads); pack = {col*128, v_half2}
__global__ void k_scatter(const int* __restrict__ rows,
                          const int* __restrict__ cols,
                          const float* __restrict__ vals, int e) {
    int i = (blockIdx.x * blockDim.x + threadIdx.x) * 4;
    if (i + 3 < e) {
        int4   r4 = __ldcs(reinterpret_cast<const int4*>(rows + i));
        int4   c4 = __ldcs(reinterpret_cast<const int4*>(cols + i));
        float4 v4 = __ldcs(reinterpret_cast<const float4*>(vals + i));
        int p;
        p = atomicAdd(&g_cursor[r4.x], 1); g_epack[p] = make_int2(c4.x << 7, half2bits(v4.x));
        p = atomicAdd(&g_cursor[r4.y], 1); g_epack[p] = make_int2(c4.y << 7, half2bits(v4.y));
        p = atomicAdd(&g_cursor[r4.z], 1); g_epack[p] = make_int2(c4.z << 7, half2bits(v4.z));
        p = atomicAdd(&g_cursor[r4.w], 1); g_epack[p] = make_int2(c4.w << 7, half2bits(v4.w));
    } else {
        for (; i < e; i++) {
            int p = atomicAdd(&g_cursor[rows[i]], 1);
            g_epack[p] = make_int2(cols[i] << 7, half2bits(vals[i]));
        }
    }
}

// zero-pad each row's edge list up to a multiple of 16 with {0, 0.0h} fillers:
// filler gathers read node 0 (broadcast, L1-hot) * 0.0 == exact zero contribution.
__global__ void k_pad(int n) {
    int r = blockIdx.x * blockDim.x + threadIdx.x;
    if (r >= n) return;
    int start = r * PAD;
    int c = g_cursor[r];
    int fin = start + (((c - start) + 15) & ~15);
    for (int i = c; i < fin; i++) g_epack[i] = make_int2(0, 0);
}

// ---------------------------------------------------------------------------
// Shared SpMM core (R12 loop structure, FROZEN): warp = 1 row; 4 groups of 8
// lanes; lane owns 16B of the 128B fp16 row. 16 edges/iter: both pack int4s
// (default cache policy -- __ldcs here measured SLOWER) and all four gather
// LDG.128s issued up front, then TWO INDEPENDENT 2-edge HFMA2 chunks, each
// flushed immediately into PACKED f32x2 accumulators (add.rn.f32x2 halves the
// flush-add instruction count vs scalar FADD).
__device__ __forceinline__ void spmm_row(const char* xb, int g, int start, int end,
                                         float2& o0, float2& o1, float2& o2, float2& o3) {
    unsigned long long f0 = 0ull, f1 = 0ull, f2 = 0ull, f3 = 0ull;

    int fin = start + (((end - start) + 15) & ~15);
    for (int e = start; e < fin; e += 16) {
        int4 pa = *reinterpret_cast<const int4*>(&g_epack[e + 2 * g]);
        int4 pb = *reinterpret_cast<const int4*>(&g_epack[e + 8 + 2 * g]);
        uint4 h0 = *reinterpret_cast<const uint4*>(xb + (uint32_t)pa.x);
        uint4 h1 = *reinterpret_cast<const uint4*>(xb + (uint32_t)pa.z);
        uint4 h2 = *reinterpret_cast<const uint4*>(xb + (uint32_t)pb.x);
        uint4 h3 = *reinterpret_cast<const uint4*>(xb + (uint32_t)pb.z);
        __half2 v0 = i2h(pa.y), v1 = i2h(pa.w);
        __half2 v2 = i2h(pb.y), v3 = i2h(pb.w);

        // chunk A: edges from pa
        __half2 c0 = __hmul2(v0, u2h(h0.x));
        __half2 c1 = __hmul2(v0, u2h(h0.y));
        __half2 c2 = __hmul2(v0, u2h(h0.z));
        __half2 c3 = __hmul2(v0, u2h(h0.w));
        c0 = __hfma2(v1, u2h(h1.x), c0);
        c1 = __hfma2(v1, u2h(h1.y), c1);
        c2 = __hfma2(v1, u2h(h1.z), c2);
        c3 = __hfma2(v1, u2h(h1.w), c3);
        acc_h2(f0, c0);
        acc_h2(f1, c1);
        acc_h2(f2, c2);
        acc_h2(f3, c3);

        // chunk B: edges from pb (independent of chunk A)
        c0 = __hmul2(v2, u2h(h2.x));
        c1 = __hmul2(v2, u2h(h2.y));
        c2 = __hmul2(v2, u2h(h2.z));
        c3 = __hmul2(v2, u2h(h2.w));
        c0 = __hfma2(v3, u2h(h3.x), c0);
        c1 = __hfma2(v3, u2h(h3.y), c1);
        c2 = __hfma2(v3, u2h(h3.z), c2);
        c3 = __hfma2(v3, u2h(h3.w), c3);
        acc_h2(f0, c0);
        acc_h2(f1, c1);
        acc_h2(f2, c2);
        acc_h2(f3, c3);
    }

    o0 = unpack64(f0);
    o1 = unpack64(f1);
    o2 = unpack64(f2);
    o3 = unpack64(f3);

    #pragma unroll
    for (int off = 8; off <= 16; off <<= 1) {
        o0.x += __shfl_xor_sync(0xffffffffu, o0.x, off);
        o0.y += __shfl_xor_sync(0xffffffffu, o0.y, off);
        o1.x += __shfl_xor_sync(0xffffffffu, o1.x, off);
        o1.y += __shfl_xor_sync(0xffffffffu, o1.y, off);
        o2.x += __shfl_xor_sync(0xffffffffu, o2.x, off);
        o2.y += __shfl_xor_sync(0xffffffffu, o2.y, off);
        o3.x += __shfl_xor_sync(0xffffffffu, o3.x, off);
        o3.y += __shfl_xor_sync(0xffffffffu, o3.y, off);
    }
}

// Layers 1-2: fp32 row -> stacked slot (streamed; re-read only once, much later)
// + fp16 mirror for the next layer (normal store; gathered next layer -> keep in L2).
__global__ __launch_bounds__(256, 8) void k_spmm12(const __half2* __restrict__ xh,
                                                   float*         __restrict__ yf,
                                                   __half2*       __restrict__ yh,
                                                   int n) {
    int gw = (blockIdx.x * blockDim.x + threadIdx.x) >> 5;
    if (gw >= n) return;
    int lane = threadIdx.x & 31;
    int g    = lane >> 3;
    int sub  = lane & 7;
    const char* xb = reinterpret_cast<const char*>(xh) + sub * 16;

    float2 f0, f1, f2, f3;
    spmm_row(xb, g, gw * PAD, __ldg(&g_cursor[gw]), f0, f1, f2, f3);

    if (g == 0) {
        size_t rb = (size_t)gw * 256 + sub * 8;
        __stcs(reinterpret_cast<float4*>(yf + rb),     make_float4(f0.x, f0.y, f1.x, f1.y));
        __stcs(reinterpret_cast<float4*>(yf + rb + 4), make_float4(f2.x, f2.y, f3.x, f3.y));

        __half2 h0 = __float22half2_rn(f0);
        __half2 h1 = __float22half2_rn(f1);
        __half2 h2 = __float22half2_rn(f2);
        __half2 h3 = __float22half2_rn(f3);
        uint4 hv;
        hv.x = *reinterpret_cast<uint32_t*>(&h0);
        hv.y = *reinterpret_cast<uint32_t*>(&h1);
        hv.z = *reinterpret_cast<uint32_t*>(&h2);
        hv.w = *reinterpret_cast<uint32_t*>(&h3);
        *reinterpret_cast<uint4*>(yh + (size_t)gw * 32 + sub * 4) = hv;
    }
}

// Layer 3 + fused epilogue. Final outputs (slot3, slot0, mean) are never
// re-read by any kernel -> __stcs streaming stores keep L2 for the gathers.
__global__ __launch_bounds__(256, 8) void k_spmm3(const __half2* __restrict__ xh,
                                                  const float*   __restrict__ emb,
                                                  float*         __restrict__ mean,
                                                  float*         __restrict__ stacked,
                                                  int n) {
    int gw = (blockIdx.x * blockDim.x + threadIdx.x) >> 5;
    if (gw >= n) return;
    int lane = threadIdx.x & 31;
    int g    = lane >> 3;
    int sub  = lane & 7;
    const char* xb = reinterpret_cast<const char*>(xh) + sub * 16;

    float2 f0, f1, f2, f3;
    spmm_row(xb, g, gw * PAD, __ldg(&g_cursor[gw]), f0, f1, f2, f3);

    if (g == 0) {
        float4 o0 = make_float4(f0.x, f0.y, f1.x, f1.y);
        float4 o1 = make_float4(f2.x, f2.y, f3.x, f3.y);
        size_t eb = (size_t)gw * 64 + sub * 8;
        size_t sb = (size_t)gw * 256 + sub * 8;

        __stcs(reinterpret_cast<float4*>(stacked + sb + 192),     o0);   // slot 3
        __stcs(reinterpret_cast<float4*>(stacked + sb + 192 + 4), o1);

        float4 a0 = *reinterpret_cast<const float4*>(emb + eb);
        float4 a1 = *reinterpret_cast<const float4*>(emb + eb + 4);
        float4 b0 = __ldcs(reinterpret_cast<const float4*>(stacked + sb + 64));
        float4 b1 = __ldcs(reinterpret_cast<const float4*>(stacked + sb + 68));
        float4 c0 = __ldcs(reinterpret_cast<const float4*>(stacked + sb + 128));
        float4 c1 = __ldcs(reinterpret_cast<const float4*>(stacked + sb + 132));
        __stcs(reinterpret_cast<float4*>(stacked + sb),     a0);         // slot 0
        __stcs(reinterpret_cast<float4*>(stacked + sb + 4), a1);

        float4 m0, m1;
        m0.x = 0.25f * (a0.x + b0.x + c0.x + o0.x);
        m0.y = 0.25f * (a0.y + b0.y + c0.y + o0.y);
        m0.z = 0.25f * (a0.z + b0.z + c0.z + o0.z);
        m0.w = 0.25f * (a0.w + b0.w + c0.w + o0.w);
        m1.x = 0.25f * (a1.x + b1.x + c1.x + o1.x);
        m1.y = 0.25f * (a1.y + b1.y + c1.y + o1.y);
        m1.z = 0.25f * (a1.z + b1.z + c1.z + o1.z);
        m1.w = 0.25f * (a1.w + b1.w + c1.w + o1.w);
        __stcs(reinterpret_cast<float4*>(mean + eb),     m0);
        __stcs(reinterpret_cast<float4*>(mean + eb + 4), m1);
    }
}

extern "C" void kernel_launch(void* const* d_in, const int* in_sizes, int n_in,
                              void* d_out, int out_size) {
    const float* emb  = (const float*)d_in[0];
    const int*   rows = (const int*)  d_in[1];
    const int*   cols = (const int*)  d_in[2];
    const float* vals = (const float*)d_in[3];
    float* out = (float*)d_out;

    int N = in_sizes[0] / DIM;
    int E = in_sizes[1];
    if (N > MAXN) N = MAXN;
    if (E > MAXE) E = MAXE;

    float* mean    = out;
    float* stacked = out + (size_t)N * DIM;   // [N, 4, 64]

    __half2* xh0;  cudaGetSymbolAddress((void**)&xh0, g_xh);
    __half2* xh1 = xh0 + MAXN * DIM / 2;

    k_prep   <<<(N * 32 + 255) / 256, 256>>>(emb, xh0, N);
    k_scatter<<<(E / 4 + 256) / 256, 256>>>(rows, cols, vals, E);
    k_pad    <<<(N + 255) / 256, 256>>>(N);

    int spmm_blocks = (N * 32 + 255) / 256;   // warp per row
    k_spmm12<<<spmm_blocks, 256>>>(xh0, stacked + 1 * DIM, xh1, N);
    k_spmm12<<<spmm_blocks, 256>>>(xh1, stacked + 2 * DIM, xh0, N);
    k_spmm3 <<<spmm_blocks, 256>>>(xh0, emb, mean, stacked, N);
}